// round 11
// baseline (speedup 1.0000x reference)
#include <cuda_runtime.h>
#include <cuda_bf16.h>
#include <cuda_fp16.h>

#define NMAX 100000
#define EMAX 1600000
#define NGRAPH 256
#define SCAN_B 256

// ---------------- static scratch (no allocation allowed) ----------------
__device__ int    g_degi[NMAX];
__device__ float  g_dinv[NMAX];
__device__ float  g_dinv2[NMAX];
__device__ int2   g_edge[EMAX];
__device__ int    g_rowptr[NMAX + 1];
__device__ int    g_tmp[NMAX];
__device__ int    g_partial[(NMAX + SCAN_B - 1) / SCAN_B + 1];
__device__ int    g_fill[NMAX];
__device__ float2 g_adj[EMAX];     // .x = src index bits, .y = norm weight
__device__ int    g_b32[NMAX];
__device__ __half g_xh[(size_t)NMAX * 64];   // fp16 input features
__device__ __half g_yh[(size_t)NMAX * 64];   // fp16 gather outputs (GEMM inputs)
__device__ __half g_th[(size_t)NMAX * 64];   // fp16 GEMM outputs (gather inputs)
__device__ float  g_h1[(size_t)NMAX * 128];
__device__ float  g_pool[NGRAPH * 32];
__device__ float  g_cnt[NGRAPH];
__device__ int    g_flag_ei;   // 1 = int64 data, 0 = int32 data
__device__ int    g_flag_b;

// ---------------- combined zeroing (one launch) ----------------
__global__ void k_zero_all(int* degi, int* fill, float* pool, float* cnt, int n) {
    int i = blockIdx.x * blockDim.x + threadIdx.x;
    if (i < n) { degi[i] = 0; fill[i] = 0; }
    if (i < NGRAPH * 32) pool[i] = 0.f;
    if (i < NGRAPH) cnt[i] = 0.f;
}

// ---------------- dtype detection: both arrays, one launch --------------
__global__ void k_detect2(const long long* __restrict__ ei, int cnt_ei, long long nmax,
                          const long long* __restrict__ batch, long long start_b,
                          int cnt_b, int* flag_ei, int* flag_b) {
    const long long* p;
    long long start, maxval;
    int count;
    int* flag;
    if (blockIdx.x == 0) { p = ei;    start = 0;       count = cnt_ei; maxval = nmax;   flag = flag_ei; }
    else                 { p = batch; start = start_b; count = cnt_b;  maxval = NGRAPH; flag = flag_b;  }
    __shared__ int bad;
    if (threadIdx.x == 0) bad = 0;
    __syncthreads();
    for (int i = threadIdx.x; i < count; i += blockDim.x) {
        long long v = p[start + i];
        if (v < 0 || v >= maxval) bad = 1;  // benign race
    }
    __syncthreads();
    if (threadIdx.x == 0) *flag = bad ? 0 : 1;
}

// ---------------- prep ----------------
__global__ void k_prep_edges(const void* __restrict__ ei, int2* __restrict__ edge,
                             int* degi, int E, int n, const int* __restrict__ flag) {
    int i = blockIdx.x * blockDim.x + threadIdx.x;
    if (i >= E) return;
    int s, d;
    if (*flag) {
        const long long* p = (const long long*)ei;
        s = (int)p[i];
        d = (int)p[(size_t)E + i];
    } else {
        const int* p = (const int*)ei;
        s = p[i];
        d = p[(size_t)E + i];
    }
    if ((unsigned)s >= (unsigned)n) s = 0;  // defensive: never trap
    if ((unsigned)d >= (unsigned)n) d = 0;
    edge[i] = make_int2(s, d);
    atomicAdd(&degi[d], 1);
}

__global__ void k_batch_cvt(const void* __restrict__ batch, int* __restrict__ b32,
                            int n, const int* __restrict__ flag) {
    int i = blockIdx.x * blockDim.x + threadIdx.x;
    if (i >= n) return;
    int b = (*flag) ? (int)((const long long*)batch)[i] : ((const int*)batch)[i];
    if ((unsigned)b >= (unsigned)NGRAPH) b = 0;
    b32[i] = b;
}

__global__ void k_dinv(const int* __restrict__ degi, float* __restrict__ dinv,
                       float* __restrict__ dinv2, int n) {
    int i = blockIdx.x * blockDim.x + threadIdx.x;
    if (i >= n) return;
    float r = rsqrtf(1.0f + (float)degi[i]);
    dinv[i] = r;
    dinv2[i] = r * r;
}

// x (f32) -> xh (fp16), vectorized
__global__ void k_cvt_x(const float4* __restrict__ X, __half2* __restrict__ Xh, int n4) {
    int i = blockIdx.x * blockDim.x + threadIdx.x;
    if (i >= n4) return;
    float4 v = __ldg(&X[i]);
    Xh[i * 2 + 0] = __floats2half2_rn(v.x, v.y);
    Xh[i * 2 + 1] = __floats2half2_rn(v.z, v.w);
}

// ---------------- prefix sum (exclusive) over degi -> rowptr ------------
__global__ void k_scan1(const int* __restrict__ degi, int* __restrict__ tmp,
                        int* __restrict__ partial, int n) {
    __shared__ int sh[SCAN_B];
    int t = threadIdx.x;
    int i = blockIdx.x * SCAN_B + t;
    int val = (i < n) ? degi[i] : 0;
    sh[t] = val;
    __syncthreads();
    for (int off = 1; off < SCAN_B; off <<= 1) {
        int x = (t >= off) ? sh[t - off] : 0;
        __syncthreads();
        sh[t] += x;
        __syncthreads();
    }
    if (i < n) tmp[i] = sh[t] - val;              // exclusive within block
    if (t == SCAN_B - 1) partial[blockIdx.x] = sh[t];
}

__global__ void k_scan_part(int* partial, int nb) {
    __shared__ int sh[512];
    __shared__ int carry;
    int t = threadIdx.x;
    if (t == 0) carry = 0;
    __syncthreads();
    for (int base = 0; base < nb; base += 512) {
        int idx = base + t;
        int val = (idx < nb) ? partial[idx] : 0;
        sh[t] = val;
        __syncthreads();
        for (int off = 1; off < 512; off <<= 1) {
            int x = (t >= off) ? sh[t - off] : 0;
            __syncthreads();
            sh[t] += x;
            __syncthreads();
        }
        if (idx < nb) partial[idx] = sh[t] - val + carry;
        __syncthreads();
        if (t == 0) carry += sh[511];
        __syncthreads();
    }
}

__global__ void k_scan_add(const int* __restrict__ tmp, const int* __restrict__ partial,
                           int* __restrict__ rowptr, int n, int E) {
    int i = blockIdx.x * blockDim.x + threadIdx.x;
    if (i < n) rowptr[i] = tmp[i] + partial[i / SCAN_B];
    if (i == 0) rowptr[n] = E;
}

__global__ void k_fill(const int2* __restrict__ edge, const int* __restrict__ rowptr,
                       int* __restrict__ fill, const float* __restrict__ dinv,
                       float2* __restrict__ adj, int E) {
    int i = blockIdx.x * blockDim.x + threadIdx.x;
    if (i >= E) return;
    int2 ed = edge[i];
    int pos = rowptr[ed.y] + atomicAdd(&fill[ed.y], 1);
    adj[pos] = make_float2(__int_as_float(ed.x), dinv[ed.x] * dinv[ed.y]);
}

// ---------------- CSR gather, software-pipelined unroll-4 ----------------
// fp16 in, fp16 out; one warp per dst node; lane owns __half2. F=64.
__global__ void __launch_bounds__(256)
k_gather64h(const __half2* __restrict__ X, __half2* __restrict__ Y,
            const int* __restrict__ rowptr, const float2* __restrict__ adj,
            const float* __restrict__ dinv2, int n) {
    int warp = (blockIdx.x * 256 + threadIdx.x) >> 5;
    int lane = threadIdx.x & 31;
    if (warp >= n) return;
    int start = __ldg(&rowptr[warp]);
    int end   = __ldg(&rowptr[warp + 1]);
    float sw = __ldg(&dinv2[warp]);
    float2 a = __half22float2(__ldg(X + (size_t)warp * 32 + lane));
    float2 acc = make_float2(a.x * sw, a.y * sw);

    int i = start;
    float2 e0, e1, e2, e3;
    bool have4 = (i + 3 < end);
    if (have4) {
        e0 = __ldg(&adj[i]);     e1 = __ldg(&adj[i + 1]);
        e2 = __ldg(&adj[i + 2]); e3 = __ldg(&adj[i + 3]);
    }
    while (have4) {
        int ni = i + 4;
        bool next4 = (ni + 3 < end);
        float2 f0, f1, f2, f3;
        if (next4) {  // prefetch next adj batch BEFORE waiting on X loads
            f0 = __ldg(&adj[ni]);     f1 = __ldg(&adj[ni + 1]);
            f2 = __ldg(&adj[ni + 2]); f3 = __ldg(&adj[ni + 3]);
        }
        float2 v0 = __half22float2(__ldg(X + (size_t)__float_as_int(e0.x) * 32 + lane));
        float2 v1 = __half22float2(__ldg(X + (size_t)__float_as_int(e1.x) * 32 + lane));
        float2 v2 = __half22float2(__ldg(X + (size_t)__float_as_int(e2.x) * 32 + lane));
        float2 v3 = __half22float2(__ldg(X + (size_t)__float_as_int(e3.x) * 32 + lane));
        acc.x += v0.x * e0.y; acc.y += v0.y * e0.y;
        acc.x += v1.x * e1.y; acc.y += v1.y * e1.y;
        acc.x += v2.x * e2.y; acc.y += v2.y * e2.y;
        acc.x += v3.x * e3.y; acc.y += v3.y * e3.y;
        e0 = f0; e1 = f1; e2 = f2; e3 = f3;
        i = ni; have4 = next4;
    }
    for (; i < end; i++) {
        float2 e = __ldg(&adj[i]);
        float2 v = __half22float2(__ldg(X + (size_t)__float_as_int(e.x) * 32 + lane));
        acc.x += v.x * e.y; acc.y += v.y * e.y;
    }
    Y[(size_t)warp * 32 + lane] = __floats2half2_rn(acc.x, acc.y);
}

// F=32 fp16 gather fused with bias+relu+mean-pool (final layer), pipelined.
__global__ void __launch_bounds__(256)
k_gather32h_pool(const __half* __restrict__ X,
                 const int* __restrict__ rowptr, const float2* __restrict__ adj,
                 const float* __restrict__ dinv2, const int* __restrict__ batch,
                 const float* __restrict__ b4, float* __restrict__ pool,
                 float* __restrict__ cnt, int n) {
    int warp = (blockIdx.x * 256 + threadIdx.x) >> 5;
    int lane = threadIdx.x & 31;
    if (warp >= n) return;
    int start = __ldg(&rowptr[warp]);
    int end   = __ldg(&rowptr[warp + 1]);
    float acc = __half2float(__ldg(X + (size_t)warp * 32 + lane)) * __ldg(&dinv2[warp]);

    int i = start;
    float2 e0, e1, e2, e3;
    bool have4 = (i + 3 < end);
    if (have4) {
        e0 = __ldg(&adj[i]);     e1 = __ldg(&adj[i + 1]);
        e2 = __ldg(&adj[i + 2]); e3 = __ldg(&adj[i + 3]);
    }
    while (have4) {
        int ni = i + 4;
        bool next4 = (ni + 3 < end);
        float2 f0, f1, f2, f3;
        if (next4) {
            f0 = __ldg(&adj[ni]);     f1 = __ldg(&adj[ni + 1]);
            f2 = __ldg(&adj[ni + 2]); f3 = __ldg(&adj[ni + 3]);
        }
        float v0 = __half2float(__ldg(X + (size_t)__float_as_int(e0.x) * 32 + lane));
        float v1 = __half2float(__ldg(X + (size_t)__float_as_int(e1.x) * 32 + lane));
        float v2 = __half2float(__ldg(X + (size_t)__float_as_int(e2.x) * 32 + lane));
        float v3 = __half2float(__ldg(X + (size_t)__float_as_int(e3.x) * 32 + lane));
        acc += v0 * e0.y + v1 * e1.y + v2 * e2.y + v3 * e3.y;
        e0 = f0; e1 = f1; e2 = f2; e3 = f3;
        i = ni; have4 = next4;
    }
    for (; i < end; i++) {
        float2 e = __ldg(&adj[i]);
        acc += __half2float(__ldg(X + (size_t)__float_as_int(e.x) * 32 + lane)) * e.y;
    }
    int b = __ldg(&batch[warp]);
    float v = fmaxf(acc + __ldg(&b4[lane]), 0.f);
    atomicAdd(&pool[b * 32 + lane], v);
    if (lane == 0) atomicAdd(&cnt[b], 1.0f);
}

// ---------------- tensor-core GEMM: Y = act(X @ W), bf16 2-term split ---
__device__ __forceinline__ void split2(float x0, float x1, unsigned& hi, unsigned& lo) {
    __nv_bfloat16 h0 = __float2bfloat16_rn(x0);
    __nv_bfloat16 h1 = __float2bfloat16_rn(x1);
    __nv_bfloat16 l0 = __float2bfloat16_rn(x0 - __bfloat162float(h0));
    __nv_bfloat16 l1 = __float2bfloat16_rn(x1 - __bfloat162float(h1));
    hi = (unsigned)__bfloat16_as_ushort(h0) | ((unsigned)__bfloat16_as_ushort(h1) << 16);
    lo = (unsigned)__bfloat16_as_ushort(l0) | ((unsigned)__bfloat16_as_ushort(l1) << 16);
}

__device__ __forceinline__ void mma16816(float* c, const unsigned* a,
                                         unsigned b0, unsigned b1) {
    asm volatile("mma.sync.aligned.m16n8k16.row.col.f32.bf16.bf16.f32 "
                 "{%0,%1,%2,%3}, {%4,%5,%6,%7}, {%8,%9}, {%0,%1,%2,%3};"
                 : "+f"(c[0]), "+f"(c[1]), "+f"(c[2]), "+f"(c[3])
                 : "r"(a[0]), "r"(a[1]), "r"(a[2]), "r"(a[3]), "r"(b0), "r"(b1));
}

// INHALF: X is fp16. OUTHALF: write fp16.
template <int KIN, int KOUT, bool INACT, bool OUTACT, bool INHALF, bool OUTHALF>
__global__ void __launch_bounds__(256)
k_gemm_tc(const void* __restrict__ Xv, const float* __restrict__ W,
          const float* __restrict__ bin, const float* __restrict__ bout,
          void* __restrict__ Yv, int n) {
    constexpr int KS = KIN / 16;   // k-steps
    constexpr int NJ = KOUT / 8;   // n-tiles
    __shared__ uint4 Wp[KS * NJ * 32];   // fragment-order packed W (hi,hi,lo,lo)
    __shared__ float bins[KIN];
    __shared__ float bouts[KOUT];
    int tid = threadIdx.x;
    int lane = tid & 31;
    int warp = tid >> 5;
    int g = lane >> 2;      // groupID (0-7)
    int tg = lane & 3;      // thread-in-group

    if (INACT)  for (int i = tid; i < KIN;  i += 256) bins[i]  = bin[i];
    if (OUTACT) for (int i = tid; i < KOUT; i += 256) bouts[i] = bout[i];

    for (int e = tid; e < KS * NJ * 32; e += 256) {
        int l  = e & 31;
        int j  = (e >> 5) % NJ;
        int ks = e / (32 * NJ);
        int col = j * 8 + (l >> 2);
        int k0  = ks * 16 + (l & 3) * 2;
        float w00 = W[(k0 + 0) * KOUT + col];
        float w01 = W[(k0 + 1) * KOUT + col];
        float w10 = W[(k0 + 8) * KOUT + col];
        float w11 = W[(k0 + 9) * KOUT + col];
        uint4 p;
        split2(w00, w01, p.x, p.z);
        split2(w10, w11, p.y, p.w);
        Wp[e] = p;
    }
    __syncthreads();

    int rowBase = blockIdx.x * 128 + warp * 16;
    int r0 = rowBase + g;
    int r1 = r0 + 8;
    bool v0 = (r0 < n), v1 = (r1 < n);

    unsigned ahi[KS * 4], alo[KS * 4];
#pragma unroll
    for (int ks = 0; ks < KS; ks++) {
        int c0 = ks * 16 + tg * 2;
        float2 z = make_float2(0.f, 0.f);
        float2 x00, x01, x10, x11;
        if (INHALF) {
            const __half2* xr0 = (const __half2*)Xv + (size_t)r0 * (KIN / 2);
            const __half2* xr1 = (const __half2*)Xv + (size_t)r1 * (KIN / 2);
            x00 = v0 ? __half22float2(xr0[c0 / 2])     : z;
            x01 = v0 ? __half22float2(xr0[c0 / 2 + 4]) : z;
            x10 = v1 ? __half22float2(xr1[c0 / 2])     : z;
            x11 = v1 ? __half22float2(xr1[c0 / 2 + 4]) : z;
        } else {
            const float* xr0 = (const float*)Xv + (size_t)r0 * KIN;
            const float* xr1 = (const float*)Xv + (size_t)r1 * KIN;
            x00 = v0 ? *(const float2*)(xr0 + c0)     : z;
            x01 = v0 ? *(const float2*)(xr0 + c0 + 8) : z;
            x10 = v1 ? *(const float2*)(xr1 + c0)     : z;
            x11 = v1 ? *(const float2*)(xr1 + c0 + 8) : z;
        }
        if (INACT) {
            x00.x = fmaxf(x00.x + bins[c0],     0.f);
            x00.y = fmaxf(x00.y + bins[c0 + 1], 0.f);
            x01.x = fmaxf(x01.x + bins[c0 + 8], 0.f);
            x01.y = fmaxf(x01.y + bins[c0 + 9], 0.f);
            x10.x = fmaxf(x10.x + bins[c0],     0.f);
            x10.y = fmaxf(x10.y + bins[c0 + 1], 0.f);
            x11.x = fmaxf(x11.x + bins[c0 + 8], 0.f);
            x11.y = fmaxf(x11.y + bins[c0 + 9], 0.f);
        }
        split2(x00.x, x00.y, ahi[ks * 4 + 0], alo[ks * 4 + 0]);
        split2(x10.x, x10.y, ahi[ks * 4 + 1], alo[ks * 4 + 1]);
        split2(x01.x, x01.y, ahi[ks * 4 + 2], alo[ks * 4 + 2]);
        split2(x11.x, x11.y, ahi[ks * 4 + 3], alo[ks * 4 + 3]);
    }

#pragma unroll
    for (int j = 0; j < NJ; j++) {
        float c[4] = {0.f, 0.f, 0.f, 0.f};
#pragma unroll
        for (int ks = 0; ks < KS; ks++) {
            uint4 wp = Wp[(ks * NJ + j) * 32 + lane];
            mma16816(c, &ahi[ks * 4], wp.x, wp.y);   // hi*hi
            mma16816(c, &ahi[ks * 4], wp.z, wp.w);   // hi*lo
            mma16816(c, &alo[ks * 4], wp.x, wp.y);   // lo*hi
        }
        int col0 = j * 8 + tg * 2;
        if (OUTACT) {
            c[0] = fmaxf(c[0] + bouts[col0],     0.f);
            c[1] = fmaxf(c[1] + bouts[col0 + 1], 0.f);
            c[2] = fmaxf(c[2] + bouts[col0],     0.f);
            c[3] = fmaxf(c[3] + bouts[col0 + 1], 0.f);
        }
        if (OUTHALF) {
            __half2* Y = (__half2*)Yv;
            if (v0) Y[((size_t)r0 * KOUT + col0) / 2] = __floats2half2_rn(c[0], c[1]);
            if (v1) Y[((size_t)r1 * KOUT + col0) / 2] = __floats2half2_rn(c[2], c[3]);
        } else {
            float* Y = (float*)Yv;
            if (v0) *(float2*)(Y + (size_t)r0 * KOUT + col0) = make_float2(c[0], c[1]);
            if (v1) *(float2*)(Y + (size_t)r1 * KOUT + col0) = make_float2(c[2], c[3]);
        }
    }
}

// ---------------- final FC ----------------
__global__ void k_final(const float* __restrict__ pool, const float* __restrict__ cnt,
                        const float* __restrict__ Wfc, const float* __restrict__ bfc,
                        float* __restrict__ out) {
    int g = threadIdx.x;
    if (g >= NGRAPH) return;
    float s = 0.f;
#pragma unroll
    for (int f = 0; f < 32; f++) s += pool[g * 32 + f] * Wfc[f];
    out[g] = s / fmaxf(cnt[g], 1.0f) + bfc[0];
}

// ---------------- host ----------------
extern "C" void kernel_launch(void* const* d_in, const int* in_sizes, int n_in,
                              void* d_out, int out_size) {
    const float* x     = (const float*)d_in[0];
    const void*  ei    = d_in[1];
    const void*  batch = d_in[2];

    int base = -1;
    for (int i = 3; i + 9 < n_in; i++) {
        if (in_sizes[i] == 8192 && in_sizes[i + 1] == 128 &&
            in_sizes[i + 2] == 8192 && in_sizes[i + 3] == 64 &&
            in_sizes[i + 4] == 4096 && in_sizes[i + 5] == 64 &&
            in_sizes[i + 6] == 2048 && in_sizes[i + 7] == 32 &&
            in_sizes[i + 8] == 32 && in_sizes[i + 9] == 1) {
            base = i;
            break;
        }
    }
    if (base < 0) base = (n_in >= 14) ? 4 : 3;  // fallback

    const float* W1  = (const float*)d_in[base + 0];
    const float* b1  = (const float*)d_in[base + 1];
    const float* W2  = (const float*)d_in[base + 2];
    const float* b2  = (const float*)d_in[base + 3];
    const float* W3  = (const float*)d_in[base + 4];
    const float* b3  = (const float*)d_in[base + 5];
    const float* W4  = (const float*)d_in[base + 6];
    const float* b4  = (const float*)d_in[base + 7];
    const float* Wfc = (const float*)d_in[base + 8];
    const float* bfc = (const float*)d_in[base + 9];
    float* out = (float*)d_out;

    int n = in_sizes[0] / 64;
    int E = in_sizes[1] / 2;

    float *dinv, *dinv2, *h1, *pool, *cnt;
    __half *xh, *yh, *th;
    float2* adj;
    int2* edge;
    int *degi, *rowptr, *tmp, *partial, *fill, *b32, *flag_ei, *flag_b;
    cudaGetSymbolAddress((void**)&degi,    g_degi);
    cudaGetSymbolAddress((void**)&dinv,    g_dinv);
    cudaGetSymbolAddress((void**)&dinv2,   g_dinv2);
    cudaGetSymbolAddress((void**)&edge,    g_edge);
    cudaGetSymbolAddress((void**)&rowptr,  g_rowptr);
    cudaGetSymbolAddress((void**)&tmp,     g_tmp);
    cudaGetSymbolAddress((void**)&partial, g_partial);
    cudaGetSymbolAddress((void**)&fill,    g_fill);
    cudaGetSymbolAddress((void**)&adj,     g_adj);
    cudaGetSymbolAddress((void**)&b32,     g_b32);
    cudaGetSymbolAddress((void**)&xh,      g_xh);
    cudaGetSymbolAddress((void**)&yh,      g_yh);
    cudaGetSymbolAddress((void**)&th,      g_th);
    cudaGetSymbolAddress((void**)&h1,      g_h1);
    cudaGetSymbolAddress((void**)&pool,    g_pool);
    cudaGetSymbolAddress((void**)&cnt,     g_cnt);
    cudaGetSymbolAddress((void**)&flag_ei, g_flag_ei);
    cudaGetSymbolAddress((void**)&flag_b,  g_flag_b);

    const int TB = 256;
    auto cdiv = [](long long a, long long b) { return (int)((a + b - 1) / b); };
    int nb = cdiv(n, SCAN_B);

    // ---- prep ----
    k_zero_all<<<cdiv(n, TB), TB>>>(degi, fill, pool, cnt, n);
    {
        int cnt_ei = (E / 2 < 4096) ? E / 2 : 4096;
        int cnt_b = (n / 2 < 4096) ? n / 2 : 4096;
        long long start_b = (long long)(n / 2) - cnt_b;
        k_detect2<<<2, 256>>>((const long long*)ei, cnt_ei, n,
                              (const long long*)batch, start_b, cnt_b,
                              flag_ei, flag_b);
    }
    k_prep_edges<<<cdiv(E, TB), TB>>>(ei, edge, degi, E, n, flag_ei);
    k_dinv<<<cdiv(n, TB), TB>>>(degi, dinv, dinv2, n);
    k_cvt_x<<<cdiv((long long)n * 16, TB), TB>>>((const float4*)x, (__half2*)xh, n * 16);
    k_scan1<<<nb, SCAN_B>>>(degi, tmp, partial, n);
    k_scan_part<<<1, 512>>>(partial, nb);
    k_scan_add<<<cdiv(n, TB), TB>>>(tmp, partial, rowptr, n, E);
    k_fill<<<cdiv(E, TB), TB>>>(edge, rowptr, fill, dinv, adj, E);
    k_batch_cvt<<<cdiv(n, TB), TB>>>(batch, b32, n, flag_b);

    int gblocks = cdiv((long long)n * 32, TB);  // one warp per node
    int mblocks = cdiv(n, 128);                 // 128 rows per GEMM block

    // ---- layer 1: aggregate xh (64) -> yh, GEMM 64->128 (f32 out) ----
    k_gather64h<<<gblocks, TB>>>((const __half2*)xh, (__half2*)yh, rowptr, adj, dinv2, n);
    k_gemm_tc<64, 128, false, true, true, false><<<mblocks, 256>>>(yh, W1, nullptr, b1, h1, n);

    // ---- layer 2: GEMM 128->64 (fp16 out) -> th, aggregate -> yh ----
    k_gemm_tc<128, 64, false, false, false, true><<<mblocks, 256>>>(h1, W2, nullptr, nullptr, th, n);
    k_gather64h<<<gblocks, TB>>>((const __half2*)th, (__half2*)yh, rowptr, adj, dinv2, n);

    // ---- layer 3: relu(yh+b2) @ W3 (64->64, fp16 out) -> th, aggregate -> yh ----
    k_gemm_tc<64, 64, true, false, true, true><<<mblocks, 256>>>(yh, W3, b2, nullptr, th, n);
    k_gather64h<<<gblocks, TB>>>((const __half2*)th, (__half2*)yh, rowptr, adj, dinv2, n);

    // ---- layer 4: relu(yh+b3) @ W4 (64->32, fp16 out) -> th, fused gather+pool ----
    k_gemm_tc<64, 32, true, false, true, true><<<mblocks, 256>>>(yh, W4, b3, nullptr, th, n);
    k_gather32h_pool<<<gblocks, TB>>>(th, rowptr, adj, dinv2, b32, b4, pool, cnt, n);

    // ---- final FC ----
    k_final<<<1, 256>>>(pool, cnt, Wfc, bfc, out);
}

// round 12
// speedup vs baseline: 1.0540x; 1.0540x over previous
#include <cuda_runtime.h>
#include <cuda_bf16.h>
#include <cuda_fp16.h>

#define NMAX 100000
#define EMAX 1600000
#define NGRAPH 256
#define SCAN_B 256

// ---------------- static scratch (no allocation allowed) ----------------
__device__ int    g_degi[NMAX];
__device__ float  g_dinv[NMAX];
__device__ float  g_dinv2[NMAX];
__device__ int2   g_edge[EMAX];
__device__ int    g_rowptr[NMAX + 1];
__device__ int    g_tmp[NMAX];
__device__ int    g_partial[(NMAX + SCAN_B - 1) / SCAN_B + 1];
__device__ int    g_fill[NMAX];
__device__ float2 g_adj[EMAX];     // .x = src index bits, .y = norm weight
__device__ int    g_b32[NMAX];
__device__ __half g_xh[(size_t)NMAX * 64];    // fp16 input features
__device__ __half g_th[(size_t)NMAX * 64];    // fp16 GEMM outputs (gather inputs)
__device__ __half g_h1h[(size_t)NMAX * 128];  // fp16 layer-1 activations
__device__ float  g_y [(size_t)NMAX * 64];    // f32 gather outputs (GEMM inputs)
__device__ float  g_pool[NGRAPH * 32];
__device__ float  g_cnt[NGRAPH];
__device__ int    g_flag_ei;   // 1 = int64 data, 0 = int32 data
__device__ int    g_flag_b;

// ---------------- launch 1: zero + dtype-detect + x->fp16 ---------------
// Block roles: [0]=detect ei, [1]=detect batch, [2,2+ZB)=zero, rest=cvt.
__global__ void k_prep0(int* degi, int* fill, float* pool, float* cnt, int n,
                        const long long* __restrict__ ei, int cnt_ei,
                        const long long* __restrict__ batch, long long start_b, int cnt_b,
                        int* flag_ei, int* flag_b,
                        const float4* __restrict__ X, __half2* __restrict__ Xh,
                        int ZB) {
    int bid = blockIdx.x;
    int tid = threadIdx.x;
    if (bid < 2) {
        const long long* p = bid ? batch : ei;
        long long start = bid ? start_b : 0;
        int count = bid ? cnt_b : cnt_ei;
        long long maxval = bid ? NGRAPH : n;
        int* flag = bid ? flag_b : flag_ei;
        __shared__ int bad;
        if (tid == 0) bad = 0;
        __syncthreads();
        for (int i = tid; i < count; i += blockDim.x) {
            long long v = p[start + i];
            if (v < 0 || v >= maxval) bad = 1;  // benign race
        }
        __syncthreads();
        if (tid == 0) *flag = bad ? 0 : 1;
    } else if (bid < 2 + ZB) {
        int i = (bid - 2) * 256 + tid;
        if (i < n) { degi[i] = 0; fill[i] = 0; }
        if (i < NGRAPH * 32) pool[i] = 0.f;
        if (i < NGRAPH) cnt[i] = 0.f;
    } else {
        int i = (bid - 2 - ZB) * 256 + tid;
        if (i < n * 16) {
            float4 v = __ldg(&X[i]);
            Xh[i * 2 + 0] = __floats2half2_rn(v.x, v.y);
            Xh[i * 2 + 1] = __floats2half2_rn(v.z, v.w);
        }
    }
}

// ---------------- launch 2: edge decode + degree ------------------------
__global__ void k_prep_edges(const void* __restrict__ ei, int2* __restrict__ edge,
                             int* degi, int E, int n, const int* __restrict__ flag) {
    int i = blockIdx.x * blockDim.x + threadIdx.x;
    if (i >= E) return;
    int s, d;
    if (*flag) {
        const long long* p = (const long long*)ei;
        s = (int)p[i];
        d = (int)p[(size_t)E + i];
    } else {
        const int* p = (const int*)ei;
        s = p[i];
        d = p[(size_t)E + i];
    }
    if ((unsigned)s >= (unsigned)n) s = 0;  // defensive: never trap
    if ((unsigned)d >= (unsigned)n) d = 0;
    edge[i] = make_int2(s, d);
    atomicAdd(&degi[d], 1);
}

// ---------------- launch 3: block scan + dinv ---------------------------
__global__ void k_scan1d(const int* __restrict__ degi, int* __restrict__ tmp,
                         int* __restrict__ partial, float* __restrict__ dinv,
                         float* __restrict__ dinv2, int n) {
    __shared__ int sh[SCAN_B];
    int t = threadIdx.x;
    int i = blockIdx.x * SCAN_B + t;
    int val = (i < n) ? degi[i] : 0;
    if (i < n) {
        float r = rsqrtf(1.0f + (float)val);
        dinv[i] = r;
        dinv2[i] = r * r;
    }
    sh[t] = val;
    __syncthreads();
    for (int off = 1; off < SCAN_B; off <<= 1) {
        int x = (t >= off) ? sh[t - off] : 0;
        __syncthreads();
        sh[t] += x;
        __syncthreads();
    }
    if (i < n) tmp[i] = sh[t] - val;              // exclusive within block
    if (t == SCAN_B - 1) partial[blockIdx.x] = sh[t];
}

__global__ void k_scan_part(int* partial, int nb) {
    __shared__ int sh[512];
    __shared__ int carry;
    int t = threadIdx.x;
    if (t == 0) carry = 0;
    __syncthreads();
    for (int base = 0; base < nb; base += 512) {
        int idx = base + t;
        int val = (idx < nb) ? partial[idx] : 0;
        sh[t] = val;
        __syncthreads();
        for (int off = 1; off < 512; off <<= 1) {
            int x = (t >= off) ? sh[t - off] : 0;
            __syncthreads();
            sh[t] += x;
            __syncthreads();
        }
        if (idx < nb) partial[idx] = sh[t] - val + carry;
        __syncthreads();
        if (t == 0) carry += sh[511];
        __syncthreads();
    }
}

__global__ void k_scan_add(const int* __restrict__ tmp, const int* __restrict__ partial,
                           int* __restrict__ rowptr, int n, int E) {
    int i = blockIdx.x * blockDim.x + threadIdx.x;
    if (i < n) rowptr[i] = tmp[i] + partial[i / SCAN_B];
    if (i == 0) rowptr[n] = E;
}

// ---------------- launch 6: CSR fill + batch convert --------------------
__global__ void k_fill_batch(const int2* __restrict__ edge, const int* __restrict__ rowptr,
                             int* __restrict__ fill, const float* __restrict__ dinv,
                             float2* __restrict__ adj, int E, int FB,
                             const void* __restrict__ batch, int* __restrict__ b32,
                             int n, const int* __restrict__ flag_b) {
    int bid = blockIdx.x;
    int tid = threadIdx.x;
    if (bid < FB) {
        int i = bid * 256 + tid;
        if (i >= E) return;
        int2 ed = edge[i];
        int pos = rowptr[ed.y] + atomicAdd(&fill[ed.y], 1);
        adj[pos] = make_float2(__int_as_float(ed.x), dinv[ed.x] * dinv[ed.y]);
    } else {
        int i = (bid - FB) * 256 + tid;
        if (i >= n) return;
        int b = (*flag_b) ? (int)((const long long*)batch)[i] : ((const int*)batch)[i];
        if ((unsigned)b >= (unsigned)NGRAPH) b = 0;
        b32[i] = b;
    }
}

// ---------------- CSR gather (R10-proven: unroll-2, fp16 in, f32 out) ---
__global__ void __launch_bounds__(256)
k_gather64h(const __half2* __restrict__ X, float* __restrict__ Y,
            const int* __restrict__ rowptr, const float2* __restrict__ adj,
            const float* __restrict__ dinv2, int n) {
    int warp = (blockIdx.x * 256 + threadIdx.x) >> 5;
    int lane = threadIdx.x & 31;
    if (warp >= n) return;
    int start = __ldg(&rowptr[warp]);
    int end   = __ldg(&rowptr[warp + 1]);
    float sw = __ldg(&dinv2[warp]);
    float2 a = __half22float2(__ldg(X + (size_t)warp * 32 + lane));
    float2 acc = make_float2(a.x * sw, a.y * sw);
    int i = start;
    for (; i + 1 < end; i += 2) {
        float2 e0 = __ldg(&adj[i]);
        float2 e1 = __ldg(&adj[i + 1]);
        float2 v0 = __half22float2(__ldg(X + (size_t)__float_as_int(e0.x) * 32 + lane));
        float2 v1 = __half22float2(__ldg(X + (size_t)__float_as_int(e1.x) * 32 + lane));
        acc.x += v0.x * e0.y; acc.y += v0.y * e0.y;
        acc.x += v1.x * e1.y; acc.y += v1.y * e1.y;
    }
    if (i < end) {
        float2 e0 = __ldg(&adj[i]);
        float2 v0 = __half22float2(__ldg(X + (size_t)__float_as_int(e0.x) * 32 + lane));
        acc.x += v0.x * e0.y; acc.y += v0.y * e0.y;
    }
    ((float2*)Y)[(size_t)warp * 32 + lane] = acc;
}

// F=32 fp16 gather fused with bias+relu+mean-pool (final layer).
__global__ void __launch_bounds__(256)
k_gather32h_pool(const __half* __restrict__ X,
                 const int* __restrict__ rowptr, const float2* __restrict__ adj,
                 const float* __restrict__ dinv2, const int* __restrict__ batch,
                 const float* __restrict__ b4, float* __restrict__ pool,
                 float* __restrict__ cnt, int n) {
    int warp = (blockIdx.x * 256 + threadIdx.x) >> 5;
    int lane = threadIdx.x & 31;
    if (warp >= n) return;
    int start = __ldg(&rowptr[warp]);
    int end   = __ldg(&rowptr[warp + 1]);
    float acc = __half2float(__ldg(X + (size_t)warp * 32 + lane)) * __ldg(&dinv2[warp]);
    int i = start;
    for (; i + 1 < end; i += 2) {
        float2 e0 = __ldg(&adj[i]);
        float2 e1 = __ldg(&adj[i + 1]);
        float v0 = __half2float(__ldg(X + (size_t)__float_as_int(e0.x) * 32 + lane));
        float v1 = __half2float(__ldg(X + (size_t)__float_as_int(e1.x) * 32 + lane));
        acc += v0 * e0.y + v1 * e1.y;
    }
    if (i < end) {
        float2 e0 = __ldg(&adj[i]);
        acc += __half2float(__ldg(X + (size_t)__float_as_int(e0.x) * 32 + lane)) * e0.y;
    }
    int b = __ldg(&batch[warp]);
    float v = fmaxf(acc + __ldg(&b4[lane]), 0.f);
    atomicAdd(&pool[b * 32 + lane], v);
    if (lane == 0) atomicAdd(&cnt[b], 1.0f);
}

// ---------------- tensor-core GEMM: Y = act(X @ W), bf16 2-term split ---
__device__ __forceinline__ void split2(float x0, float x1, unsigned& hi, unsigned& lo) {
    __nv_bfloat16 h0 = __float2bfloat16_rn(x0);
    __nv_bfloat16 h1 = __float2bfloat16_rn(x1);
    __nv_bfloat16 l0 = __float2bfloat16_rn(x0 - __bfloat162float(h0));
    __nv_bfloat16 l1 = __float2bfloat16_rn(x1 - __bfloat162float(h1));
    hi = (unsigned)__bfloat16_as_ushort(h0) | ((unsigned)__bfloat16_as_ushort(h1) << 16);
    lo = (unsigned)__bfloat16_as_ushort(l0) | ((unsigned)__bfloat16_as_ushort(l1) << 16);
}

__device__ __forceinline__ void mma16816(float* c, const unsigned* a,
                                         unsigned b0, unsigned b1) {
    asm volatile("mma.sync.aligned.m16n8k16.row.col.f32.bf16.bf16.f32 "
                 "{%0,%1,%2,%3}, {%4,%5,%6,%7}, {%8,%9}, {%0,%1,%2,%3};"
                 : "+f"(c[0]), "+f"(c[1]), "+f"(c[2]), "+f"(c[3])
                 : "r"(a[0]), "r"(a[1]), "r"(a[2]), "r"(a[3]), "r"(b0), "r"(b1));
}

// INHALF: X is fp16. OUTHALF: write fp16.
template <int KIN, int KOUT, bool INACT, bool OUTACT, bool INHALF, bool OUTHALF>
__global__ void __launch_bounds__(256)
k_gemm_tc(const void* __restrict__ Xv, const float* __restrict__ W,
          const float* __restrict__ bin, const float* __restrict__ bout,
          void* __restrict__ Yv, int n) {
    constexpr int KS = KIN / 16;   // k-steps
    constexpr int NJ = KOUT / 8;   // n-tiles
    __shared__ uint4 Wp[KS * NJ * 32];   // fragment-order packed W (hi,hi,lo,lo)
    __shared__ float bins[KIN];
    __shared__ float bouts[KOUT];
    int tid = threadIdx.x;
    int lane = tid & 31;
    int warp = tid >> 5;
    int g = lane >> 2;      // groupID (0-7)
    int tg = lane & 3;      // thread-in-group

    if (INACT)  for (int i = tid; i < KIN;  i += 256) bins[i]  = bin[i];
    if (OUTACT) for (int i = tid; i < KOUT; i += 256) bouts[i] = bout[i];

    for (int e = tid; e < KS * NJ * 32; e += 256) {
        int l  = e & 31;
        int j  = (e >> 5) % NJ;
        int ks = e / (32 * NJ);
        int col = j * 8 + (l >> 2);
        int k0  = ks * 16 + (l & 3) * 2;
        float w00 = W[(k0 + 0) * KOUT + col];
        float w01 = W[(k0 + 1) * KOUT + col];
        float w10 = W[(k0 + 8) * KOUT + col];
        float w11 = W[(k0 + 9) * KOUT + col];
        uint4 p;
        split2(w00, w01, p.x, p.z);
        split2(w10, w11, p.y, p.w);
        Wp[e] = p;
    }
    __syncthreads();

    int rowBase = blockIdx.x * 128 + warp * 16;
    int r0 = rowBase + g;
    int r1 = r0 + 8;
    bool v0 = (r0 < n), v1 = (r1 < n);

    unsigned ahi[KS * 4], alo[KS * 4];
#pragma unroll
    for (int ks = 0; ks < KS; ks++) {
        int c0 = ks * 16 + tg * 2;
        float2 z = make_float2(0.f, 0.f);
        float2 x00, x01, x10, x11;
        if (INHALF) {
            const __half2* xr0 = (const __half2*)Xv + (size_t)r0 * (KIN / 2);
            const __half2* xr1 = (const __half2*)Xv + (size_t)r1 * (KIN / 2);
            x00 = v0 ? __half22float2(xr0[c0 / 2])     : z;
            x01 = v0 ? __half22float2(xr0[c0 / 2 + 4]) : z;
            x10 = v1 ? __half22float2(xr1[c0 / 2])     : z;
            x11 = v1 ? __half22float2(xr1[c0 / 2 + 4]) : z;
        } else {
            const float* xr0 = (const float*)Xv + (size_t)r0 * KIN;
            const float* xr1 = (const float*)Xv + (size_t)r1 * KIN;
            x00 = v0 ? *(const float2*)(xr0 + c0)     : z;
            x01 = v0 ? *(const float2*)(xr0 + c0 + 8) : z;
            x10 = v1 ? *(const float2*)(xr1 + c0)     : z;
            x11 = v1 ? *(const float2*)(xr1 + c0 + 8) : z;
        }
        if (INACT) {
            x00.x = fmaxf(x00.x + bins[c0],     0.f);
            x00.y = fmaxf(x00.y + bins[c0 + 1], 0.f);
            x01.x = fmaxf(x01.x + bins[c0 + 8], 0.f);
            x01.y = fmaxf(x01.y + bins[c0 + 9], 0.f);
            x10.x = fmaxf(x10.x + bins[c0],     0.f);
            x10.y = fmaxf(x10.y + bins[c0 + 1], 0.f);
            x11.x = fmaxf(x11.x + bins[c0 + 8], 0.f);
            x11.y = fmaxf(x11.y + bins[c0 + 9], 0.f);
        }
        split2(x00.x, x00.y, ahi[ks * 4 + 0], alo[ks * 4 + 0]);
        split2(x10.x, x10.y, ahi[ks * 4 + 1], alo[ks * 4 + 1]);
        split2(x01.x, x01.y, ahi[ks * 4 + 2], alo[ks * 4 + 2]);
        split2(x11.x, x11.y, ahi[ks * 4 + 3], alo[ks * 4 + 3]);
    }

#pragma unroll
    for (int j = 0; j < NJ; j++) {
        float c[4] = {0.f, 0.f, 0.f, 0.f};
#pragma unroll
        for (int ks = 0; ks < KS; ks++) {
            uint4 wp = Wp[(ks * NJ + j) * 32 + lane];
            mma16816(c, &ahi[ks * 4], wp.x, wp.y);   // hi*hi
            mma16816(c, &ahi[ks * 4], wp.z, wp.w);   // hi*lo
            mma16816(c, &alo[ks * 4], wp.x, wp.y);   // lo*hi
        }
        int col0 = j * 8 + tg * 2;
        if (OUTACT) {
            c[0] = fmaxf(c[0] + bouts[col0],     0.f);
            c[1] = fmaxf(c[1] + bouts[col0 + 1], 0.f);
            c[2] = fmaxf(c[2] + bouts[col0],     0.f);
            c[3] = fmaxf(c[3] + bouts[col0 + 1], 0.f);
        }
        if (OUTHALF) {
            __half2* Y = (__half2*)Yv;
            if (v0) Y[((size_t)r0 * KOUT + col0) / 2] = __floats2half2_rn(c[0], c[1]);
            if (v1) Y[((size_t)r1 * KOUT + col0) / 2] = __floats2half2_rn(c[2], c[3]);
        } else {
            float* Y = (float*)Yv;
            if (v0) *(float2*)(Y + (size_t)r0 * KOUT + col0) = make_float2(c[0], c[1]);
            if (v1) *(float2*)(Y + (size_t)r1 * KOUT + col0) = make_float2(c[2], c[3]);
        }
    }
}

// ---------------- final FC ----------------
__global__ void k_final(const float* __restrict__ pool, const float* __restrict__ cnt,
                        const float* __restrict__ Wfc, const float* __restrict__ bfc,
                        float* __restrict__ out) {
    int g = threadIdx.x;
    if (g >= NGRAPH) return;
    float s = 0.f;
#pragma unroll
    for (int f = 0; f < 32; f++) s += pool[g * 32 + f] * Wfc[f];
    out[g] = s / fmaxf(cnt[g], 1.0f) + bfc[0];
}

// ---------------- host ----------------
extern "C" void kernel_launch(void* const* d_in, const int* in_sizes, int n_in,
                              void* d_out, int out_size) {
    const float* x     = (const float*)d_in[0];
    const void*  ei    = d_in[1];
    const void*  batch = d_in[2];

    int base = -1;
    for (int i = 3; i + 9 < n_in; i++) {
        if (in_sizes[i] == 8192 && in_sizes[i + 1] == 128 &&
            in_sizes[i + 2] == 8192 && in_sizes[i + 3] == 64 &&
            in_sizes[i + 4] == 4096 && in_sizes[i + 5] == 64 &&
            in_sizes[i + 6] == 2048 && in_sizes[i + 7] == 32 &&
            in_sizes[i + 8] == 32 && in_sizes[i + 9] == 1) {
            base = i;
            break;
        }
    }
    if (base < 0) base = (n_in >= 14) ? 4 : 3;  // fallback

    const float* W1  = (const float*)d_in[base + 0];
    const float* b1  = (const float*)d_in[base + 1];
    const float* W2  = (const float*)d_in[base + 2];
    const float* b2  = (const float*)d_in[base + 3];
    const float* W3  = (const float*)d_in[base + 4];
    const float* b3  = (const float*)d_in[base + 5];
    const float* W4  = (const float*)d_in[base + 6];
    const float* b4  = (const float*)d_in[base + 7];
    const float* Wfc = (const float*)d_in[base + 8];
    const float* bfc = (const float*)d_in[base + 9];
    float* out = (float*)d_out;

    int n = in_sizes[0] / 64;
    int E = in_sizes[1] / 2;

    float *dinv, *dinv2, *pool, *cnt, *y;
    __half *xh, *th, *h1h;
    float2* adj;
    int2* edge;
    int *degi, *rowptr, *tmp, *partial, *fill, *b32, *flag_ei, *flag_b;
    cudaGetSymbolAddress((void**)&degi,    g_degi);
    cudaGetSymbolAddress((void**)&dinv,    g_dinv);
    cudaGetSymbolAddress((void**)&dinv2,   g_dinv2);
    cudaGetSymbolAddress((void**)&edge,    g_edge);
    cudaGetSymbolAddress((void**)&rowptr,  g_rowptr);
    cudaGetSymbolAddress((void**)&tmp,     g_tmp);
    cudaGetSymbolAddress((void**)&partial, g_partial);
    cudaGetSymbolAddress((void**)&fill,    g_fill);
    cudaGetSymbolAddress((void**)&adj,     g_adj);
    cudaGetSymbolAddress((void**)&b32,     g_b32);
    cudaGetSymbolAddress((void**)&xh,      g_xh);
    cudaGetSymbolAddress((void**)&th,      g_th);
    cudaGetSymbolAddress((void**)&h1h,     g_h1h);
    cudaGetSymbolAddress((void**)&y,       g_y);
    cudaGetSymbolAddress((void**)&pool,    g_pool);
    cudaGetSymbolAddress((void**)&cnt,     g_cnt);
    cudaGetSymbolAddress((void**)&flag_ei, g_flag_ei);
    cudaGetSymbolAddress((void**)&flag_b,  g_flag_b);

    const int TB = 256;
    auto cdiv = [](long long a, long long b) { return (int)((a + b - 1) / b); };
    int nb = cdiv(n, SCAN_B);

    // ---- prep (6 launches) ----
    {
        int cnt_ei = (E / 2 < 4096) ? E / 2 : 4096;
        int cnt_b = (n / 2 < 4096) ? n / 2 : 4096;
        long long start_b = (long long)(n / 2) - cnt_b;
        int ZB = cdiv(n, TB);
        int CB = cdiv((long long)n * 16, TB);
        k_prep0<<<2 + ZB + CB, TB>>>(degi, fill, pool, cnt, n,
                                     (const long long*)ei, cnt_ei,
                                     (const long long*)batch, start_b, cnt_b,
                                     flag_ei, flag_b,
                                     (const float4*)x, (__half2*)xh, ZB);
    }
    k_prep_edges<<<cdiv(E, TB), TB>>>(ei, edge, degi, E, n, flag_ei);
    k_scan1d<<<nb, SCAN_B>>>(degi, tmp, partial, dinv, dinv2, n);
    k_scan_part<<<1, 512>>>(partial, nb);
    k_scan_add<<<cdiv(n, TB), TB>>>(tmp, partial, rowptr, n, E);
    {
        int FB = cdiv(E, TB);
        int BB = cdiv(n, TB);
        k_fill_batch<<<FB + BB, TB>>>(edge, rowptr, fill, dinv, adj, E, FB,
                                      batch, b32, n, flag_b);
    }

    int gblocks = cdiv((long long)n * 32, TB);  // one warp per node
    int mblocks = cdiv(n, 128);                 // 128 rows per GEMM block

    // ---- layer 1: aggregate xh (64) -> y (f32), GEMM 64->128 (fp16 out) ----
    k_gather64h<<<gblocks, TB>>>((const __half2*)xh, y, rowptr, adj, dinv2, n);
    k_gemm_tc<64, 128, false, true, false, true><<<mblocks, 256>>>(y, W1, nullptr, b1, h1h, n);

    // ---- layer 2: GEMM 128->64 (fp16 in+out) -> th, aggregate -> y ----
    k_gemm_tc<128, 64, false, false, true, true><<<mblocks, 256>>>(h1h, W2, nullptr, nullptr, th, n);
    k_gather64h<<<gblocks, TB>>>((const __half2*)th, y, rowptr, adj, dinv2, n);

    // ---- layer 3: relu(y+b2) @ W3 (64->64, fp16 out) -> th, aggregate -> y ----
    k_gemm_tc<64, 64, true, false, false, true><<<mblocks, 256>>>(y, W3, b2, nullptr, th, n);
    k_gather64h<<<gblocks, TB>>>((const __half2*)th, y, rowptr, adj, dinv2, n);

    // ---- layer 4: relu(y+b3) @ W4 (64->32, fp16 out) -> th, fused gather+pool ----
    k_gemm_tc<64, 32, true, false, false, true><<<mblocks, 256>>>(y, W4, b3, nullptr, th, n);
    k_gather32h_pool<<<gblocks, TB>>>(th, rowptr, adj, dinv2, b32, b4, pool, cnt, n);

    // ---- final FC ----
    k_final<<<1, 256>>>(pool, cnt, Wfc, bfc, out);
}

// round 13
// speedup vs baseline: 1.0934x; 1.0374x over previous
#include <cuda_runtime.h>
#include <cuda_fp16.h>

#define NMAX 100000
#define EMAX 1600000
#define NGRAPH 256
#define SCAN_B 256

// ---------------- static scratch (no allocation allowed) ----------------
__device__ int    g_degi[NMAX];
__device__ float  g_dinv[NMAX];
__device__ float  g_dinv2[NMAX];
__device__ int2   g_edge[EMAX];
__device__ int    g_rowptr[NMAX + 1];
__device__ int    g_tmp[NMAX];
__device__ int    g_partial[(NMAX + SCAN_B - 1) / SCAN_B + 1];
__device__ int    g_fill[NMAX];
__device__ float2 g_adj[EMAX];     // .x = src index bits, .y = norm weight
__device__ int    g_b32[NMAX];
__device__ __half g_xh[(size_t)NMAX * 64];    // fp16 input features
__device__ __half g_yh[(size_t)NMAX * 64];    // fp16 gather outputs (GEMM inputs)
__device__ __half g_th[(size_t)NMAX * 64];    // fp16 GEMM outputs (gather inputs)
__device__ __half g_h1h[(size_t)NMAX * 128];  // fp16 layer-1 activations
__device__ float  g_pool[NGRAPH * 32];
__device__ float  g_cnt[NGRAPH];
__device__ int    g_flag_ei;   // 1 = int64 data, 0 = int32 data
__device__ int    g_flag_b;

// ---------------- launch 1: zero + dtype-detect + x->fp16 ---------------
__global__ void k_prep0(int* degi, int* fill, float* pool, float* cnt, int n,
                        const long long* __restrict__ ei, int cnt_ei,
                        const long long* __restrict__ batch, long long start_b, int cnt_b,
                        int* flag_ei, int* flag_b,
                        const float4* __restrict__ X, __half2* __restrict__ Xh,
                        int ZB) {
    int bid = blockIdx.x;
    int tid = threadIdx.x;
    if (bid < 2) {
        const long long* p = bid ? batch : ei;
        long long start = bid ? start_b : 0;
        int count = bid ? cnt_b : cnt_ei;
        long long maxval = bid ? NGRAPH : n;
        int* flag = bid ? flag_b : flag_ei;
        __shared__ int bad;
        if (tid == 0) bad = 0;
        __syncthreads();
        for (int i = tid; i < count; i += blockDim.x) {
            long long v = p[start + i];
            if (v < 0 || v >= maxval) bad = 1;  // benign race
        }
        __syncthreads();
        if (tid == 0) *flag = bad ? 0 : 1;
    } else if (bid < 2 + ZB) {
        int i = (bid - 2) * 256 + tid;
        if (i < n) { degi[i] = 0; fill[i] = 0; }
        if (i < NGRAPH * 32) pool[i] = 0.f;
        if (i < NGRAPH) cnt[i] = 0.f;
    } else {
        int i = (bid - 2 - ZB) * 256 + tid;
        if (i < n * 16) {
            float4 v = __ldg(&X[i]);
            Xh[i * 2 + 0] = __floats2half2_rn(v.x, v.y);
            Xh[i * 2 + 1] = __floats2half2_rn(v.z, v.w);
        }
    }
}

// ---------------- launch 2: edge decode + degree ------------------------
__global__ void k_prep_edges(const void* __restrict__ ei, int2* __restrict__ edge,
                             int* degi, int E, int n, const int* __restrict__ flag) {
    int i = blockIdx.x * blockDim.x + threadIdx.x;
    if (i >= E) return;
    int s, d;
    if (*flag) {
        const long long* p = (const long long*)ei;
        s = (int)p[i];
        d = (int)p[(size_t)E + i];
    } else {
        const int* p = (const int*)ei;
        s = p[i];
        d = p[(size_t)E + i];
    }
    if ((unsigned)s >= (unsigned)n) s = 0;  // defensive: never trap
    if ((unsigned)d >= (unsigned)n) d = 0;
    edge[i] = make_int2(s, d);
    atomicAdd(&degi[d], 1);
}

// ---------------- launch 3: block scan + dinv ---------------------------
__global__ void k_scan1d(const int* __restrict__ degi, int* __restrict__ tmp,
                         int* __restrict__ partial, float* __restrict__ dinv,
                         float* __restrict__ dinv2, int n) {
    __shared__ int sh[SCAN_B];
    int t = threadIdx.x;
    int i = blockIdx.x * SCAN_B + t;
    int val = (i < n) ? degi[i] : 0;
    if (i < n) {
        float r = rsqrtf(1.0f + (float)val);
        dinv[i] = r;
        dinv2[i] = r * r;
    }
    sh[t] = val;
    __syncthreads();
    for (int off = 1; off < SCAN_B; off <<= 1) {
        int x = (t >= off) ? sh[t - off] : 0;
        __syncthreads();
        sh[t] += x;
        __syncthreads();
    }
    if (i < n) tmp[i] = sh[t] - val;              // exclusive within block
    if (t == SCAN_B - 1) partial[blockIdx.x] = sh[t];
}

__global__ void k_scan_part(int* partial, int nb) {
    __shared__ int sh[512];
    __shared__ int carry;
    int t = threadIdx.x;
    if (t == 0) carry = 0;
    __syncthreads();
    for (int base = 0; base < nb; base += 512) {
        int idx = base + t;
        int val = (idx < nb) ? partial[idx] : 0;
        sh[t] = val;
        __syncthreads();
        for (int off = 1; off < 512; off <<= 1) {
            int x = (t >= off) ? sh[t - off] : 0;
            __syncthreads();
            sh[t] += x;
            __syncthreads();
        }
        if (idx < nb) partial[idx] = sh[t] - val + carry;
        __syncthreads();
        if (t == 0) carry += sh[511];
        __syncthreads();
    }
}

__global__ void k_scan_add(const int* __restrict__ tmp, const int* __restrict__ partial,
                           int* __restrict__ rowptr, int n, int E) {
    int i = blockIdx.x * blockDim.x + threadIdx.x;
    if (i < n) rowptr[i] = tmp[i] + partial[i / SCAN_B];
    if (i == 0) rowptr[n] = E;
}

// ---------------- launch 6: CSR fill + batch convert --------------------
__global__ void k_fill_batch(const int2* __restrict__ edge, const int* __restrict__ rowptr,
                             int* __restrict__ fill, const float* __restrict__ dinv,
                             float2* __restrict__ adj, int E, int FB,
                             const void* __restrict__ batch, int* __restrict__ b32,
                             int n, const int* __restrict__ flag_b) {
    int bid = blockIdx.x;
    int tid = threadIdx.x;
    if (bid < FB) {
        int i = bid * 256 + tid;
        if (i >= E) return;
        int2 ed = edge[i];
        int pos = rowptr[ed.y] + atomicAdd(&fill[ed.y], 1);
        adj[pos] = make_float2(__int_as_float(ed.x), dinv[ed.x] * dinv[ed.y]);
    } else {
        int i = (bid - FB) * 256 + tid;
        if (i >= n) return;
        int b = (*flag_b) ? (int)((const long long*)batch)[i] : ((const int*)batch)[i];
        if ((unsigned)b >= (unsigned)NGRAPH) b = 0;
        b32[i] = b;
    }
}

// ---------------- CSR gather (unroll-2, fp16 in, fp16 out) --------------
__global__ void __launch_bounds__(256)
k_gather64h(const __half2* __restrict__ X, __half2* __restrict__ Y,
            const int* __restrict__ rowptr, const float2* __restrict__ adj,
            const float* __restrict__ dinv2, int n) {
    int warp = (blockIdx.x * 256 + threadIdx.x) >> 5;
    int lane = threadIdx.x & 31;
    if (warp >= n) return;
    int start = __ldg(&rowptr[warp]);
    int end   = __ldg(&rowptr[warp + 1]);
    float sw = __ldg(&dinv2[warp]);
    float2 a = __half22float2(__ldg(X + (size_t)warp * 32 + lane));
    float2 acc = make_float2(a.x * sw, a.y * sw);
    int i = start;
    for (; i + 1 < end; i += 2) {
        float2 e0 = __ldg(&adj[i]);
        float2 e1 = __ldg(&adj[i + 1]);
        float2 v0 = __half22float2(__ldg(X + (size_t)__float_as_int(e0.x) * 32 + lane));
        float2 v1 = __half22float2(__ldg(X + (size_t)__float_as_int(e1.x) * 32 + lane));
        acc.x += v0.x * e0.y; acc.y += v0.y * e0.y;
        acc.x += v1.x * e1.y; acc.y += v1.y * e1.y;
    }
    if (i < end) {
        float2 e0 = __ldg(&adj[i]);
        float2 v0 = __half22float2(__ldg(X + (size_t)__float_as_int(e0.x) * 32 + lane));
        acc.x += v0.x * e0.y; acc.y += v0.y * e0.y;
    }
    Y[(size_t)warp * 32 + lane] = __floats2half2_rn(acc.x, acc.y);
}

// F=32 fp16 gather fused with bias+relu+mean-pool (final layer).
__global__ void __launch_bounds__(256)
k_gather32h_pool(const __half* __restrict__ X,
                 const int* __restrict__ rowptr, const float2* __restrict__ adj,
                 const float* __restrict__ dinv2, const int* __restrict__ batch,
                 const float* __restrict__ b4, float* __restrict__ pool,
                 float* __restrict__ cnt, int n) {
    int warp = (blockIdx.x * 256 + threadIdx.x) >> 5;
    int lane = threadIdx.x & 31;
    if (warp >= n) return;
    int start = __ldg(&rowptr[warp]);
    int end   = __ldg(&rowptr[warp + 1]);
    float acc = __half2float(__ldg(X + (size_t)warp * 32 + lane)) * __ldg(&dinv2[warp]);
    int i = start;
    for (; i + 1 < end; i += 2) {
        float2 e0 = __ldg(&adj[i]);
        float2 e1 = __ldg(&adj[i + 1]);
        float v0 = __half2float(__ldg(X + (size_t)__float_as_int(e0.x) * 32 + lane));
        float v1 = __half2float(__ldg(X + (size_t)__float_as_int(e1.x) * 32 + lane));
        acc += v0 * e0.y + v1 * e1.y;
    }
    if (i < end) {
        float2 e0 = __ldg(&adj[i]);
        acc += __half2float(__ldg(X + (size_t)__float_as_int(e0.x) * 32 + lane)) * e0.y;
    }
    int b = __ldg(&batch[warp]);
    float v = fmaxf(acc + __ldg(&b4[lane]), 0.f);
    atomicAdd(&pool[b * 32 + lane], v);
    if (lane == 0) atomicAdd(&cnt[b], 1.0f);
}

// ---------------- tensor-core GEMM: fp16 A (exact), W = fp16 hi+lo ------
// A is already fp16 (activations) -> consumed bit-exact, no split needed.
// W split: w = whi + wlo (both fp16); error ~2^-22. 2 MMAs per tile.
__device__ __forceinline__ void splith(float x0, float x1, unsigned& hi, unsigned& lo) {
    __half h0 = __float2half_rn(x0);
    __half h1 = __float2half_rn(x1);
    __half l0 = __float2half_rn(x0 - __half2float(h0));
    __half l1 = __float2half_rn(x1 - __half2float(h1));
    hi = (unsigned)__half_as_ushort(h0) | ((unsigned)__half_as_ushort(h1) << 16);
    lo = (unsigned)__half_as_ushort(l0) | ((unsigned)__half_as_ushort(l1) << 16);
}

__device__ __forceinline__ void mma16816h(float* c, const unsigned* a,
                                          unsigned b0, unsigned b1) {
    asm volatile("mma.sync.aligned.m16n8k16.row.col.f32.f16.f16.f32 "
                 "{%0,%1,%2,%3}, {%4,%5,%6,%7}, {%8,%9}, {%0,%1,%2,%3};"
                 : "+f"(c[0]), "+f"(c[1]), "+f"(c[2]), "+f"(c[3])
                 : "r"(a[0]), "r"(a[1]), "r"(a[2]), "r"(a[3]), "r"(b0), "r"(b1));
}

template <int KIN, int KOUT, bool INACT, bool OUTACT>
__global__ void __launch_bounds__(256)
k_gemm_tch(const __half2* __restrict__ X, const float* __restrict__ W,
           const float* __restrict__ bin, const float* __restrict__ bout,
           __half2* __restrict__ Y, int n) {
    constexpr int KS = KIN / 16;   // k-steps
    constexpr int NJ = KOUT / 8;   // n-tiles
    __shared__ uint4 Wp[KS * NJ * 32];    // (hi0,hi1,lo0,lo1) fragment-order
    __shared__ __half2 binh[KIN / 2];
    __shared__ float bouts[KOUT];
    int tid = threadIdx.x;
    int lane = tid & 31;
    int warp = tid >> 5;
    int g = lane >> 2;      // groupID (0-7)
    int tg = lane & 3;      // thread-in-group

    if (INACT)  for (int i = tid; i < KIN / 2; i += 256)
        binh[i] = __floats2half2_rn(bin[2 * i], bin[2 * i + 1]);
    if (OUTACT) for (int i = tid; i < KOUT; i += 256) bouts[i] = bout[i];

    for (int e = tid; e < KS * NJ * 32; e += 256) {
        int l  = e & 31;
        int j  = (e >> 5) % NJ;
        int ks = e / (32 * NJ);
        int col = j * 8 + (l >> 2);
        int k0  = ks * 16 + (l & 3) * 2;
        float w00 = W[(k0 + 0) * KOUT + col];
        float w01 = W[(k0 + 1) * KOUT + col];
        float w10 = W[(k0 + 8) * KOUT + col];
        float w11 = W[(k0 + 9) * KOUT + col];
        uint4 p;
        splith(w00, w01, p.x, p.z);
        splith(w10, w11, p.y, p.w);
        Wp[e] = p;
    }
    __syncthreads();

    int rowBase = blockIdx.x * 128 + warp * 16;
    int r0 = rowBase + g;
    int r1 = r0 + 8;
    bool v0 = (r0 < n), v1 = (r1 < n);
    const __half2* xr0 = X + (size_t)r0 * (KIN / 2);
    const __half2* xr1 = X + (size_t)r1 * (KIN / 2);
    const __half2 z2 = __floats2half2_rn(0.f, 0.f);

    unsigned a[KS * 4];
#pragma unroll
    for (int ks = 0; ks < KS; ks++) {
        int c2 = (ks * 16 + tg * 2) / 2;   // half2 index
        __half2 h00 = v0 ? xr0[c2]     : z2;
        __half2 h01 = v0 ? xr0[c2 + 4] : z2;
        __half2 h10 = v1 ? xr1[c2]     : z2;
        __half2 h11 = v1 ? xr1[c2 + 4] : z2;
        if (INACT) {
            h00 = __hmax2(__hadd2(h00, binh[c2]),     z2);
            h01 = __hmax2(__hadd2(h01, binh[c2 + 4]), z2);
            h10 = __hmax2(__hadd2(h10, binh[c2]),     z2);
            h11 = __hmax2(__hadd2(h11, binh[c2 + 4]), z2);
        }
        a[ks * 4 + 0] = *reinterpret_cast<unsigned*>(&h00);
        a[ks * 4 + 1] = *reinterpret_cast<unsigned*>(&h10);
        a[ks * 4 + 2] = *reinterpret_cast<unsigned*>(&h01);
        a[ks * 4 + 3] = *reinterpret_cast<unsigned*>(&h11);
    }

#pragma unroll
    for (int j = 0; j < NJ; j++) {
        float c[4] = {0.f, 0.f, 0.f, 0.f};
#pragma unroll
        for (int ks = 0; ks < KS; ks++) {
            uint4 wp = Wp[(ks * NJ + j) * 32 + lane];
            mma16816h(c, &a[ks * 4], wp.x, wp.y);   // A * Whi
            mma16816h(c, &a[ks * 4], wp.z, wp.w);   // A * Wlo
        }
        int col0 = j * 8 + tg * 2;
        if (OUTACT) {
            c[0] = fmaxf(c[0] + bouts[col0],     0.f);
            c[1] = fmaxf(c[1] + bouts[col0 + 1], 0.f);
            c[2] = fmaxf(c[2] + bouts[col0],     0.f);
            c[3] = fmaxf(c[3] + bouts[col0 + 1], 0.f);
        }
        if (v0) Y[((size_t)r0 * KOUT + col0) / 2] = __floats2half2_rn(c[0], c[1]);
        if (v1) Y[((size_t)r1 * KOUT + col0) / 2] = __floats2half2_rn(c[2], c[3]);
    }
}

// ---------------- final FC ----------------
__global__ void k_final(const float* __restrict__ pool, const float* __restrict__ cnt,
                        const float* __restrict__ Wfc, const float* __restrict__ bfc,
                        float* __restrict__ out) {
    int g = threadIdx.x;
    if (g >= NGRAPH) return;
    float s = 0.f;
#pragma unroll
    for (int f = 0; f < 32; f++) s += pool[g * 32 + f] * Wfc[f];
    out[g] = s / fmaxf(cnt[g], 1.0f) + bfc[0];
}

// ---------------- host ----------------
extern "C" void kernel_launch(void* const* d_in, const int* in_sizes, int n_in,
                              void* d_out, int out_size) {
    const float* x     = (const float*)d_in[0];
    const void*  ei    = d_in[1];
    const void*  batch = d_in[2];

    int base = -1;
    for (int i = 3; i + 9 < n_in; i++) {
        if (in_sizes[i] == 8192 && in_sizes[i + 1] == 128 &&
            in_sizes[i + 2] == 8192 && in_sizes[i + 3] == 64 &&
            in_sizes[i + 4] == 4096 && in_sizes[i + 5] == 64 &&
            in_sizes[i + 6] == 2048 && in_sizes[i + 7] == 32 &&
            in_sizes[i + 8] == 32 && in_sizes[i + 9] == 1) {
            base = i;
            break;
        }
    }
    if (base < 0) base = (n_in >= 14) ? 4 : 3;  // fallback

    const float* W1  = (const float*)d_in[base + 0];
    const float* b1  = (const float*)d_in[base + 1];
    const float* W2  = (const float*)d_in[base + 2];
    const float* b2  = (const float*)d_in[base + 3];
    const float* W3  = (const float*)d_in[base + 4];
    const float* b3  = (const float*)d_in[base + 5];
    const float* W4  = (const float*)d_in[base + 6];
    const float* b4  = (const float*)d_in[base + 7];
    const float* Wfc = (const float*)d_in[base + 8];
    const float* bfc = (const float*)d_in[base + 9];
    float* out = (float*)d_out;

    int n = in_sizes[0] / 64;
    int E = in_sizes[1] / 2;

    float *dinv, *dinv2, *pool, *cnt;
    __half *xh, *yh, *th, *h1h;
    float2* adj;
    int2* edge;
    int *degi, *rowptr, *tmp, *partial, *fill, *b32, *flag_ei, *flag_b;
    cudaGetSymbolAddress((void**)&degi,    g_degi);
    cudaGetSymbolAddress((void**)&dinv,    g_dinv);
    cudaGetSymbolAddress((void**)&dinv2,   g_dinv2);
    cudaGetSymbolAddress((void**)&edge,    g_edge);
    cudaGetSymbolAddress((void**)&rowptr,  g_rowptr);
    cudaGetSymbolAddress((void**)&tmp,     g_tmp);
    cudaGetSymbolAddress((void**)&partial, g_partial);
    cudaGetSymbolAddress((void**)&fill,    g_fill);
    cudaGetSymbolAddress((void**)&adj,     g_adj);
    cudaGetSymbolAddress((void**)&b32,     g_b32);
    cudaGetSymbolAddress((void**)&xh,      g_xh);
    cudaGetSymbolAddress((void**)&yh,      g_yh);
    cudaGetSymbolAddress((void**)&th,      g_th);
    cudaGetSymbolAddress((void**)&h1h,     g_h1h);
    cudaGetSymbolAddress((void**)&pool,    g_pool);
    cudaGetSymbolAddress((void**)&cnt,     g_cnt);
    cudaGetSymbolAddress((void**)&flag_ei, g_flag_ei);
    cudaGetSymbolAddress((void**)&flag_b,  g_flag_b);

    const int TB = 256;
    auto cdiv = [](long long a, long long b) { return (int)((a + b - 1) / b); };
    int nb = cdiv(n, SCAN_B);

    // ---- prep (6 launches) ----
    {
        int cnt_ei = (E / 2 < 4096) ? E / 2 : 4096;
        int cnt_b = (n / 2 < 4096) ? n / 2 : 4096;
        long long start_b = (long long)(n / 2) - cnt_b;
        int ZB = cdiv(n, TB);
        int CB = cdiv((long long)n * 16, TB);
        k_prep0<<<2 + ZB + CB, TB>>>(degi, fill, pool, cnt, n,
                                     (const long long*)ei, cnt_ei,
                                     (const long long*)batch, start_b, cnt_b,
                                     flag_ei, flag_b,
                                     (const float4*)x, (__half2*)xh, ZB);
    }
    k_prep_edges<<<cdiv(E, TB), TB>>>(ei, edge, degi, E, n, flag_ei);
    k_scan1d<<<nb, SCAN_B>>>(degi, tmp, partial, dinv, dinv2, n);
    k_scan_part<<<1, 512>>>(partial, nb);
    k_scan_add<<<cdiv(n, TB), TB>>>(tmp, partial, rowptr, n, E);
    {
        int FB = cdiv(E, TB);
        int BB = cdiv(n, TB);
        k_fill_batch<<<FB + BB, TB>>>(edge, rowptr, fill, dinv, adj, E, FB,
                                      batch, b32, n, flag_b);
    }

    int gblocks = cdiv((long long)n * 32, TB);  // one warp per node
    int mblocks = cdiv(n, 128);                 // 128 rows per GEMM block

    // ---- layer 1: aggregate xh (64) -> yh, GEMM 64->128 (+b1+relu) -> h1h ----
    k_gather64h<<<gblocks, TB>>>((const __half2*)xh, (__half2*)yh, rowptr, adj, dinv2, n);
    k_gemm_tch<64, 128, false, true><<<mblocks, 256>>>((const __half2*)yh, W1, nullptr, b1, (__half2*)h1h, n);

    // ---- layer 2: GEMM 128->64 -> th, aggregate -> yh ----
    k_gemm_tch<128, 64, false, false><<<mblocks, 256>>>((const __half2*)h1h, W2, nullptr, nullptr, (__half2*)th, n);
    k_gather64h<<<gblocks, TB>>>((const __half2*)th, (__half2*)yh, rowptr, adj, dinv2, n);

    // ---- layer 3: relu(yh+b2) @ W3 (64->64) -> th, aggregate -> yh ----
    k_gemm_tch<64, 64, true, false><<<mblocks, 256>>>((const __half2*)yh, W3, b2, nullptr, (__half2*)th, n);
    k_gather64h<<<gblocks, TB>>>((const __half2*)th, (__half2*)yh, rowptr, adj, dinv2, n);

    // ---- layer 4: relu(yh+b3) @ W4 (64->32) -> th, fused gather+pool ----
    k_gemm_tch<64, 32, true, false><<<mblocks, 256>>>((const __half2*)yh, W4, b3, nullptr, (__half2*)th, n);
    k_gather32h_pool<<<gblocks, TB>>>(th, rowptr, adj, dinv2, b32, b4, pool, cnt, n);

    // ---- final FC ----
    k_final<<<1, 256>>>(pool, cnt, Wfc, bfc, out);
}

// round 14
// speedup vs baseline: 1.1331x; 1.0363x over previous
#include <cuda_runtime.h>
#include <cuda_fp16.h>

#define NMAX 100000
#define EMAX 1600000
#define NGRAPH 256
#define SCAN_B 256

// ---------------- static scratch (no allocation allowed) ----------------
__device__ int    g_degi[NMAX];
__device__ float  g_dinv[NMAX];
__device__ float  g_dinv2[NMAX];
__device__ int2   g_edge[EMAX];
__device__ int    g_rowptr[NMAX + 1];
__device__ int    g_tmp[NMAX];
__device__ int    g_partial[(NMAX + SCAN_B - 1) / SCAN_B + 1];
__device__ int    g_fill[NMAX];
__device__ float2 g_adj[EMAX];     // .x = src index bits, .y = norm weight
__device__ int    g_b32[NMAX];
__device__ __half g_xh[(size_t)NMAX * 64];    // fp16 input features
__device__ __half g_yh[(size_t)NMAX * 64];    // fp16 gather outputs (GEMM inputs)
__device__ __half g_th[(size_t)NMAX * 64];    // fp16 GEMM outputs (gather inputs)
__device__ __half g_h1h[(size_t)NMAX * 128];  // fp16 layer-1 activations
__device__ float  g_pool[NGRAPH * 32];
__device__ float  g_cnt[NGRAPH];
__device__ int    g_flag_ei;   // 1 = int64 data, 0 = int32 data
__device__ int    g_flag_b;

// ---------------- launch 1: zero + dtype-detect + x->fp16 ---------------
__global__ void k_prep0(int* degi, int* fill, float* pool, float* cnt, int n,
                        const long long* __restrict__ ei, int cnt_ei,
                        const long long* __restrict__ batch, long long start_b, int cnt_b,
                        int* flag_ei, int* flag_b,
                        const float4* __restrict__ X, __half2* __restrict__ Xh,
                        int ZB) {
    int bid = blockIdx.x;
    int tid = threadIdx.x;
    if (bid < 2) {
        const long long* p = bid ? batch : ei;
        long long start = bid ? start_b : 0;
        int count = bid ? cnt_b : cnt_ei;
        long long maxval = bid ? NGRAPH : n;
        int* flag = bid ? flag_b : flag_ei;
        __shared__ int bad;
        if (tid == 0) bad = 0;
        __syncthreads();
        for (int i = tid; i < count; i += blockDim.x) {
            long long v = p[start + i];
            if (v < 0 || v >= maxval) bad = 1;  // benign race
        }
        __syncthreads();
        if (tid == 0) *flag = bad ? 0 : 1;
    } else if (bid < 2 + ZB) {
        int i = (bid - 2) * 256 + tid;
        if (i < n) { degi[i] = 0; fill[i] = 0; }
        if (i < NGRAPH * 32) pool[i] = 0.f;
        if (i < NGRAPH) cnt[i] = 0.f;
    } else {
        int i = (bid - 2 - ZB) * 256 + tid;
        if (i < n * 16) {
            float4 v = __ldg(&X[i]);
            Xh[i * 2 + 0] = __floats2half2_rn(v.x, v.y);
            Xh[i * 2 + 1] = __floats2half2_rn(v.z, v.w);
        }
    }
}

// ---------------- launch 2: edge decode + degree ------------------------
__global__ void k_prep_edges(const void* __restrict__ ei, int2* __restrict__ edge,
                             int* degi, int E, int n, const int* __restrict__ flag) {
    int i = blockIdx.x * blockDim.x + threadIdx.x;
    if (i >= E) return;
    int s, d;
    if (*flag) {
        const long long* p = (const long long*)ei;
        s = (int)p[i];
        d = (int)p[(size_t)E + i];
    } else {
        const int* p = (const int*)ei;
        s = p[i];
        d = p[(size_t)E + i];
    }
    if ((unsigned)s >= (unsigned)n) s = 0;  // defensive: never trap
    if ((unsigned)d >= (unsigned)n) d = 0;
    edge[i] = make_int2(s, d);
    atomicAdd(&degi[d], 1);
}

// ---------------- launch 3: block scan + dinv ---------------------------
__global__ void k_scan1d(const int* __restrict__ degi, int* __restrict__ tmp,
                         int* __restrict__ partial, float* __restrict__ dinv,
                         float* __restrict__ dinv2, int n) {
    __shared__ int sh[SCAN_B];
    int t = threadIdx.x;
    int i = blockIdx.x * SCAN_B + t;
    int val = (i < n) ? degi[i] : 0;
    if (i < n) {
        float r = rsqrtf(1.0f + (float)val);
        dinv[i] = r;
        dinv2[i] = r * r;
    }
    sh[t] = val;
    __syncthreads();
    for (int off = 1; off < SCAN_B; off <<= 1) {
        int x = (t >= off) ? sh[t - off] : 0;
        __syncthreads();
        sh[t] += x;
        __syncthreads();
    }
    if (i < n) tmp[i] = sh[t] - val;              // exclusive within block
    if (t == SCAN_B - 1) partial[blockIdx.x] = sh[t];
}

__global__ void k_scan_part(int* partial, int nb) {
    __shared__ int sh[512];
    __shared__ int carry;
    int t = threadIdx.x;
    if (t == 0) carry = 0;
    __syncthreads();
    for (int base = 0; base < nb; base += 512) {
        int idx = base + t;
        int val = (idx < nb) ? partial[idx] : 0;
        sh[t] = val;
        __syncthreads();
        for (int off = 1; off < 512; off <<= 1) {
            int x = (t >= off) ? sh[t - off] : 0;
            __syncthreads();
            sh[t] += x;
            __syncthreads();
        }
        if (idx < nb) partial[idx] = sh[t] - val + carry;
        __syncthreads();
        if (t == 0) carry += sh[511];
        __syncthreads();
    }
}

__global__ void k_scan_add(const int* __restrict__ tmp, const int* __restrict__ partial,
                           int* __restrict__ rowptr, int n, int E) {
    int i = blockIdx.x * blockDim.x + threadIdx.x;
    if (i < n) rowptr[i] = tmp[i] + partial[i / SCAN_B];
    if (i == 0) rowptr[n] = E;
}

// ---------------- launch 6: CSR fill + batch convert --------------------
__global__ void k_fill_batch(const int2* __restrict__ edge, const int* __restrict__ rowptr,
                             int* __restrict__ fill, const float* __restrict__ dinv,
                             float2* __restrict__ adj, int E, int FB,
                             const void* __restrict__ batch, int* __restrict__ b32,
                             int n, const int* __restrict__ flag_b) {
    int bid = blockIdx.x;
    int tid = threadIdx.x;
    if (bid < FB) {
        int i = bid * 256 + tid;
        if (i >= E) return;
        int2 ed = edge[i];
        int pos = rowptr[ed.y] + atomicAdd(&fill[ed.y], 1);
        adj[pos] = make_float2(__int_as_float(ed.x), dinv[ed.x] * dinv[ed.y]);
    } else {
        int i = (bid - FB) * 256 + tid;
        if (i >= n) return;
        int b = (*flag_b) ? (int)((const long long*)batch)[i] : ((const int*)batch)[i];
        if ((unsigned)b >= (unsigned)NGRAPH) b = 0;
        b32[i] = b;
    }
}

// ---------------- paired-edge CSR gather (F=64) -------------------------
// Half-warps process edges i and i+1 simultaneously; each lane loads 8B
// (4 features). One X-LDG + one adj-LDG serve TWO edges. Partial accs
// merge via shfl_down(16); 16-lane uint2 store.
__global__ void __launch_bounds__(256)
k_gather64p(const __half* __restrict__ X, __half* __restrict__ Y,
            const int* __restrict__ rowptr, const float2* __restrict__ adj,
            const float* __restrict__ dinv2, int n) {
    int warp = (blockIdx.x * 256 + threadIdx.x) >> 5;
    int lane = threadIdx.x & 31;
    int hw = lane >> 4;      // half-warp id (edge parity)
    int hl = lane & 15;      // lane within half: features [4*hl, 4*hl+4)
    if (warp >= n) return;
    int start = __ldg(&rowptr[warp]);
    int end   = __ldg(&rowptr[warp + 1]);
    float a0 = 0.f, a1 = 0.f, a2 = 0.f, a3 = 0.f;
    if (hw == 0) {  // self-loop term on low half only
        float sw = __ldg(&dinv2[warp]);
        uint2 u = __ldg((const uint2*)(X + (size_t)warp * 64) + hl);
        float2 fa = __half22float2(*(__half2*)&u.x);
        float2 fb = __half22float2(*(__half2*)&u.y);
        a0 = fa.x * sw; a1 = fa.y * sw; a2 = fb.x * sw; a3 = fb.y * sw;
    }
    for (int i = start; i < end; i += 2) {
        int e = i + hw;
        if (e < end) {
            float2 ae = __ldg(&adj[e]);
            int src = __float_as_int(ae.x);
            float w = ae.y;
            uint2 u = __ldg((const uint2*)(X + (size_t)src * 64) + hl);
            float2 fa = __half22float2(*(__half2*)&u.x);
            float2 fb = __half22float2(*(__half2*)&u.y);
            a0 += fa.x * w; a1 += fa.y * w; a2 += fb.x * w; a3 += fb.y * w;
        }
    }
    a0 += __shfl_down_sync(0xffffffffu, a0, 16);
    a1 += __shfl_down_sync(0xffffffffu, a1, 16);
    a2 += __shfl_down_sync(0xffffffffu, a2, 16);
    a3 += __shfl_down_sync(0xffffffffu, a3, 16);
    if (hw == 0) {
        uint2 o;
        *(__half2*)&o.x = __floats2half2_rn(a0, a1);
        *(__half2*)&o.y = __floats2half2_rn(a2, a3);
        ((uint2*)(Y + (size_t)warp * 64))[hl] = o;
    }
}

// Paired-edge F=32 gather fused with bias+relu+mean-pool (final layer).
// Lane owns features [2*hl, 2*hl+2) for edge parity hw.
__global__ void __launch_bounds__(256)
k_gather32p_pool(const __half* __restrict__ X,
                 const int* __restrict__ rowptr, const float2* __restrict__ adj,
                 const float* __restrict__ dinv2, const int* __restrict__ batch,
                 const float* __restrict__ b4, float* __restrict__ pool,
                 float* __restrict__ cnt, int n) {
    int warp = (blockIdx.x * 256 + threadIdx.x) >> 5;
    int lane = threadIdx.x & 31;
    int hw = lane >> 4;
    int hl = lane & 15;
    if (warp >= n) return;
    int start = __ldg(&rowptr[warp]);
    int end   = __ldg(&rowptr[warp + 1]);
    float a0 = 0.f, a1 = 0.f;
    if (hw == 0) {
        float sw = __ldg(&dinv2[warp]);
        float2 f = __half22float2(__ldg((const __half2*)(X + (size_t)warp * 32) + hl));
        a0 = f.x * sw; a1 = f.y * sw;
    }
    for (int i = start; i < end; i += 2) {
        int e = i + hw;
        if (e < end) {
            float2 ae = __ldg(&adj[e]);
            int src = __float_as_int(ae.x);
            float w = ae.y;
            float2 f = __half22float2(__ldg((const __half2*)(X + (size_t)src * 32) + hl));
            a0 += f.x * w; a1 += f.y * w;
        }
    }
    a0 += __shfl_down_sync(0xffffffffu, a0, 16);
    a1 += __shfl_down_sync(0xffffffffu, a1, 16);
    if (hw == 0) {
        int b = __ldg(&batch[warp]);
        float v0 = fmaxf(a0 + __ldg(&b4[2 * hl]),     0.f);
        float v1 = fmaxf(a1 + __ldg(&b4[2 * hl + 1]), 0.f);
        atomicAdd(&pool[b * 32 + 2 * hl],     v0);
        atomicAdd(&pool[b * 32 + 2 * hl + 1], v1);
        if (hl == 0) atomicAdd(&cnt[b], 1.0f);
    }
}

// ---------------- tensor-core GEMM: fp16 A (exact), W = fp16 hi+lo ------
__device__ __forceinline__ void splith(float x0, float x1, unsigned& hi, unsigned& lo) {
    __half h0 = __float2half_rn(x0);
    __half h1 = __float2half_rn(x1);
    __half l0 = __float2half_rn(x0 - __half2float(h0));
    __half l1 = __float2half_rn(x1 - __half2float(h1));
    hi = (unsigned)__half_as_ushort(h0) | ((unsigned)__half_as_ushort(h1) << 16);
    lo = (unsigned)__half_as_ushort(l0) | ((unsigned)__half_as_ushort(l1) << 16);
}

__device__ __forceinline__ void mma16816h(float* c, const unsigned* a,
                                          unsigned b0, unsigned b1) {
    asm volatile("mma.sync.aligned.m16n8k16.row.col.f32.f16.f16.f32 "
                 "{%0,%1,%2,%3}, {%4,%5,%6,%7}, {%8,%9}, {%0,%1,%2,%3};"
                 : "+f"(c[0]), "+f"(c[1]), "+f"(c[2]), "+f"(c[3])
                 : "r"(a[0]), "r"(a[1]), "r"(a[2]), "r"(a[3]), "r"(b0), "r"(b1));
}

template <int KIN, int KOUT, bool INACT, bool OUTACT>
__global__ void __launch_bounds__(256)
k_gemm_tch(const __half2* __restrict__ X, const float* __restrict__ W,
           const float* __restrict__ bin, const float* __restrict__ bout,
           __half2* __restrict__ Y, int n) {
    constexpr int KS = KIN / 16;   // k-steps
    constexpr int NJ = KOUT / 8;   // n-tiles
    __shared__ uint4 Wp[KS * NJ * 32];    // (hi0,hi1,lo0,lo1) fragment-order
    __shared__ __half2 binh[KIN / 2];
    __shared__ float bouts[KOUT];
    int tid = threadIdx.x;
    int lane = tid & 31;
    int warp = tid >> 5;
    int g = lane >> 2;      // groupID (0-7)
    int tg = lane & 3;      // thread-in-group

    if (INACT)  for (int i = tid; i < KIN / 2; i += 256)
        binh[i] = __floats2half2_rn(bin[2 * i], bin[2 * i + 1]);
    if (OUTACT) for (int i = tid; i < KOUT; i += 256) bouts[i] = bout[i];

    for (int e = tid; e < KS * NJ * 32; e += 256) {
        int l  = e & 31;
        int j  = (e >> 5) % NJ;
        int ks = e / (32 * NJ);
        int col = j * 8 + (l >> 2);
        int k0  = ks * 16 + (l & 3) * 2;
        float w00 = W[(k0 + 0) * KOUT + col];
        float w01 = W[(k0 + 1) * KOUT + col];
        float w10 = W[(k0 + 8) * KOUT + col];
        float w11 = W[(k0 + 9) * KOUT + col];
        uint4 p;
        splith(w00, w01, p.x, p.z);
        splith(w10, w11, p.y, p.w);
        Wp[e] = p;
    }
    __syncthreads();

    int rowBase = blockIdx.x * 128 + warp * 16;
    int r0 = rowBase + g;
    int r1 = r0 + 8;
    bool v0 = (r0 < n), v1 = (r1 < n);
    const __half2* xr0 = X + (size_t)r0 * (KIN / 2);
    const __half2* xr1 = X + (size_t)r1 * (KIN / 2);
    const __half2 z2 = __floats2half2_rn(0.f, 0.f);

    unsigned a[KS * 4];
#pragma unroll
    for (int ks = 0; ks < KS; ks++) {
        int c2 = (ks * 16 + tg * 2) / 2;   // half2 index
        __half2 h00 = v0 ? xr0[c2]     : z2;
        __half2 h01 = v0 ? xr0[c2 + 4] : z2;
        __half2 h10 = v1 ? xr1[c2]     : z2;
        __half2 h11 = v1 ? xr1[c2 + 4] : z2;
        if (INACT) {
            h00 = __hmax2(__hadd2(h00, binh[c2]),     z2);
            h01 = __hmax2(__hadd2(h01, binh[c2 + 4]), z2);
            h10 = __hmax2(__hadd2(h10, binh[c2]),     z2);
            h11 = __hmax2(__hadd2(h11, binh[c2 + 4]), z2);
        }
        a[ks * 4 + 0] = *reinterpret_cast<unsigned*>(&h00);
        a[ks * 4 + 1] = *reinterpret_cast<unsigned*>(&h10);
        a[ks * 4 + 2] = *reinterpret_cast<unsigned*>(&h01);
        a[ks * 4 + 3] = *reinterpret_cast<unsigned*>(&h11);
    }

#pragma unroll
    for (int j = 0; j < NJ; j++) {
        float c[4] = {0.f, 0.f, 0.f, 0.f};
#pragma unroll
        for (int ks = 0; ks < KS; ks++) {
            uint4 wp = Wp[(ks * NJ + j) * 32 + lane];
            mma16816h(c, &a[ks * 4], wp.x, wp.y);   // A * Whi
            mma16816h(c, &a[ks * 4], wp.z, wp.w);   // A * Wlo
        }
        int col0 = j * 8 + tg * 2;
        if (OUTACT) {
            c[0] = fmaxf(c[0] + bouts[col0],     0.f);
            c[1] = fmaxf(c[1] + bouts[col0 + 1], 0.f);
            c[2] = fmaxf(c[2] + bouts[col0],     0.f);
            c[3] = fmaxf(c[3] + bouts[col0 + 1], 0.f);
        }
        if (v0) Y[((size_t)r0 * KOUT + col0) / 2] = __floats2half2_rn(c[0], c[1]);
        if (v1) Y[((size_t)r1 * KOUT + col0) / 2] = __floats2half2_rn(c[2], c[3]);
    }
}

// ---------------- final FC ----------------
__global__ void k_final(const float* __restrict__ pool, const float* __restrict__ cnt,
                        const float* __restrict__ Wfc, const float* __restrict__ bfc,
                        float* __restrict__ out) {
    int g = threadIdx.x;
    if (g >= NGRAPH) return;
    float s = 0.f;
#pragma unroll
    for (int f = 0; f < 32; f++) s += pool[g * 32 + f] * Wfc[f];
    out[g] = s / fmaxf(cnt[g], 1.0f) + bfc[0];
}

// ---------------- host ----------------
extern "C" void kernel_launch(void* const* d_in, const int* in_sizes, int n_in,
                              void* d_out, int out_size) {
    const float* x     = (const float*)d_in[0];
    const void*  ei    = d_in[1];
    const void*  batch = d_in[2];

    int base = -1;
    for (int i = 3; i + 9 < n_in; i++) {
        if (in_sizes[i] == 8192 && in_sizes[i + 1] == 128 &&
            in_sizes[i + 2] == 8192 && in_sizes[i + 3] == 64 &&
            in_sizes[i + 4] == 4096 && in_sizes[i + 5] == 64 &&
            in_sizes[i + 6] == 2048 && in_sizes[i + 7] == 32 &&
            in_sizes[i + 8] == 32 && in_sizes[i + 9] == 1) {
            base = i;
            break;
        }
    }
    if (base < 0) base = (n_in >= 14) ? 4 : 3;  // fallback

    const float* W1  = (const float*)d_in[base + 0];
    const float* b1  = (const float*)d_in[base + 1];
    const float* W2  = (const float*)d_in[base + 2];
    const float* b2  = (const float*)d_in[base + 3];
    const float* W3  = (const float*)d_in[base + 4];
    const float* b3  = (const float*)d_in[base + 5];
    const float* W4  = (const float*)d_in[base + 6];
    const float* b4  = (const float*)d_in[base + 7];
    const float* Wfc = (const float*)d_in[base + 8];
    const float* bfc = (const float*)d_in[base + 9];
    float* out = (float*)d_out;

    int n = in_sizes[0] / 64;
    int E = in_sizes[1] / 2;

    float *dinv, *dinv2, *pool, *cnt;
    __half *xh, *yh, *th, *h1h;
    float2* adj;
    int2* edge;
    int *degi, *rowptr, *tmp, *partial, *fill, *b32, *flag_ei, *flag_b;
    cudaGetSymbolAddress((void**)&degi,    g_degi);
    cudaGetSymbolAddress((void**)&dinv,    g_dinv);
    cudaGetSymbolAddress((void**)&dinv2,   g_dinv2);
    cudaGetSymbolAddress((void**)&edge,    g_edge);
    cudaGetSymbolAddress((void**)&rowptr,  g_rowptr);
    cudaGetSymbolAddress((void**)&tmp,     g_tmp);
    cudaGetSymbolAddress((void**)&partial, g_partial);
    cudaGetSymbolAddress((void**)&fill,    g_fill);
    cudaGetSymbolAddress((void**)&adj,     g_adj);
    cudaGetSymbolAddress((void**)&b32,     g_b32);
    cudaGetSymbolAddress((void**)&xh,      g_xh);
    cudaGetSymbolAddress((void**)&yh,      g_yh);
    cudaGetSymbolAddress((void**)&th,      g_th);
    cudaGetSymbolAddress((void**)&h1h,     g_h1h);
    cudaGetSymbolAddress((void**)&pool,    g_pool);
    cudaGetSymbolAddress((void**)&cnt,     g_cnt);
    cudaGetSymbolAddress((void**)&flag_ei, g_flag_ei);
    cudaGetSymbolAddress((void**)&flag_b,  g_flag_b);

    const int TB = 256;
    auto cdiv = [](long long a, long long b) { return (int)((a + b - 1) / b); };
    int nb = cdiv(n, SCAN_B);

    // ---- prep (6 launches) ----
    {
        int cnt_ei = (E / 2 < 4096) ? E / 2 : 4096;
        int cnt_b = (n / 2 < 4096) ? n / 2 : 4096;
        long long start_b = (long long)(n / 2) - cnt_b;
        int ZB = cdiv(n, TB);
        int CB = cdiv((long long)n * 16, TB);
        k_prep0<<<2 + ZB + CB, TB>>>(degi, fill, pool, cnt, n,
                                     (const long long*)ei, cnt_ei,
                                     (const long long*)batch, start_b, cnt_b,
                                     flag_ei, flag_b,
                                     (const float4*)x, (__half2*)xh, ZB);
    }
    k_prep_edges<<<cdiv(E, TB), TB>>>(ei, edge, degi, E, n, flag_ei);
    k_scan1d<<<nb, SCAN_B>>>(degi, tmp, partial, dinv, dinv2, n);
    k_scan_part<<<1, 512>>>(partial, nb);
    k_scan_add<<<cdiv(n, TB), TB>>>(tmp, partial, rowptr, n, E);
    {
        int FB = cdiv(E, TB);
        int BB = cdiv(n, TB);
        k_fill_batch<<<FB + BB, TB>>>(edge, rowptr, fill, dinv, adj, E, FB,
                                      batch, b32, n, flag_b);
    }

    int gblocks = cdiv((long long)n * 32, TB);  // one warp per node
    int mblocks = cdiv(n, 128);                 // 128 rows per GEMM block

    // ---- layer 1: aggregate xh (64) -> yh, GEMM 64->128 (+b1+relu) -> h1h ----
    k_gather64p<<<gblocks, TB>>>(xh, yh, rowptr, adj, dinv2, n);
    k_gemm_tch<64, 128, false, true><<<mblocks, 256>>>((const __half2*)yh, W1, nullptr, b1, (__half2*)h1h, n);

    // ---- layer 2: GEMM 128->64 -> th, aggregate -> yh ----
    k_gemm_tch<128, 64, false, false><<<mblocks, 256>>>((const __half2*)h1h, W2, nullptr, nullptr, (__half2*)th, n);
    k_gather64p<<<gblocks, TB>>>(th, yh, rowptr, adj, dinv2, n);

    // ---- layer 3: relu(yh+b2) @ W3 (64->64) -> th, aggregate -> yh ----
    k_gemm_tch<64, 64, true, false><<<mblocks, 256>>>((const __half2*)yh, W3, b2, nullptr, (__half2*)th, n);
    k_gather64p<<<gblocks, TB>>>(th, yh, rowptr, adj, dinv2, n);

    // ---- layer 4: relu(yh+b3) @ W4 (64->32) -> th, fused gather+pool ----
    k_gemm_tch<64, 32, true, false><<<mblocks, 256>>>((const __half2*)yh, W4, b3, nullptr, (__half2*)th, n);
    k_gather32p_pool<<<gblocks, TB>>>(th, rowptr, adj, dinv2, b32, b4, pool, cnt, n);

    // ---- final FC ----
    k_final<<<1, 256>>>(pool, cnt, Wfc, bfc, out);
}